// round 1
// baseline (speedup 1.0000x reference)
#include <cuda_runtime.h>
#include <cstdint>

#define MAXN 50000
#define F1 128
#define F2 64

// Scratch (allocation-free rule: __device__ globals)
__device__ float g_h1[MAXN * F1];    // x @ W1
__device__ float g_agg1[MAXN * F1];  // scatter-add result, layer 1
__device__ float g_h2[MAXN * F2];    // relu(agg1+b1) @ W2
__device__ float g_agg2[MAXN * F2];  // scatter-add result, layer 2

// ---------------------------------------------------------------------------
// GEMM1: h1 = x @ W1   (M=N nodes, K=128, N=128). W1 (64KB) staged in smem.
// Each warp computes 2 rows; lane holds float4 of 4 output cols.
// ---------------------------------------------------------------------------
__global__ void gemm1_kernel(const float* __restrict__ x,
                             const float* __restrict__ W,
                             float* __restrict__ out, int nrows) {
    extern __shared__ float sW[];  // 128*128 floats
    for (int i = threadIdx.x; i < (F1 * F1) / 4; i += blockDim.x)
        ((float4*)sW)[i] = ((const float4*)W)[i];
    __syncthreads();

    const float4* sW4 = (const float4*)sW;
    int lane   = threadIdx.x & 31;
    int gwarp  = (blockIdx.x * blockDim.x + threadIdx.x) >> 5;
    int nwarps = (gridDim.x * blockDim.x) >> 5;

    for (int r0 = gwarp * 2; r0 < nrows; r0 += nwarps * 2) {
        int r1 = r0 + 1;
        bool has1 = (r1 < nrows);
        float4 acc0 = make_float4(0.f, 0.f, 0.f, 0.f);
        float4 acc1 = make_float4(0.f, 0.f, 0.f, 0.f);
        for (int k0 = 0; k0 < F1; k0 += 32) {
            float xa = x[(size_t)r0 * F1 + k0 + lane];
            float xb = has1 ? x[(size_t)r1 * F1 + k0 + lane] : 0.f;
#pragma unroll
            for (int j = 0; j < 32; j++) {
                float a = __shfl_sync(0xffffffffu, xa, j);
                float b = __shfl_sync(0xffffffffu, xb, j);
                float4 w = sW4[(k0 + j) * 32 + lane];
                acc0.x += a * w.x; acc0.y += a * w.y;
                acc0.z += a * w.z; acc0.w += a * w.w;
                acc1.x += b * w.x; acc1.y += b * w.y;
                acc1.z += b * w.z; acc1.w += b * w.w;
            }
        }
        ((float4*)out)[(size_t)r0 * 32 + lane] = acc0;
        if (has1) ((float4*)out)[(size_t)r1 * 32 + lane] = acc1;
    }
}

// ---------------------------------------------------------------------------
// Scatter layer 1: agg1[dst] += w * h1[src]   (F=128). One warp per edge,
// lane handles one float4 chunk. red.global.add.v4.f32 (no return).
// ---------------------------------------------------------------------------
__global__ void scatter128_kernel(const float* __restrict__ h,
                                  const int* __restrict__ ei,
                                  const float* __restrict__ ew,
                                  float* __restrict__ agg, int E) {
    int lane   = threadIdx.x & 31;
    int gwarp  = (blockIdx.x * blockDim.x + threadIdx.x) >> 5;
    int nwarps = (gridDim.x * blockDim.x) >> 5;

    for (int e = gwarp; e < E; e += nwarps) {
        int src = ei[e];
        int dst = ei[E + e];
        float w = ew[e];
        float4 v = ((const float4*)(h + (size_t)src * F1))[lane];
        v.x *= w; v.y *= w; v.z *= w; v.w *= w;
        float* ap = agg + (size_t)dst * F1 + lane * 4;
        asm volatile("red.global.add.v4.f32 [%0], {%1,%2,%3,%4};"
                     :: "l"(ap), "f"(v.x), "f"(v.y), "f"(v.z), "f"(v.w)
                     : "memory");
    }
}

// ---------------------------------------------------------------------------
// GEMM2: h2 = relu(agg1 + b1) @ W2  (K=128, Nout=64). W2+b1 in smem.
// Lane holds float2 (2 output cols); 2 rows per warp.
// ---------------------------------------------------------------------------
__global__ void gemm2_kernel(const float* __restrict__ in,
                             const float* __restrict__ W,
                             const float* __restrict__ b,
                             float* __restrict__ out, int nrows) {
    extern __shared__ float s[];   // 128*64 W + 128 bias
    float* sW = s;
    float* sb = s + F1 * F2;
    for (int i = threadIdx.x; i < (F1 * F2) / 4; i += blockDim.x)
        ((float4*)sW)[i] = ((const float4*)W)[i];
    if (threadIdx.x < F1) sb[threadIdx.x] = b[threadIdx.x];
    __syncthreads();

    const float2* sW2 = (const float2*)sW;
    int lane   = threadIdx.x & 31;
    int gwarp  = (blockIdx.x * blockDim.x + threadIdx.x) >> 5;
    int nwarps = (gridDim.x * blockDim.x) >> 5;

    for (int r0 = gwarp * 2; r0 < nrows; r0 += nwarps * 2) {
        int r1 = r0 + 1;
        bool has1 = (r1 < nrows);
        float2 acc0 = make_float2(0.f, 0.f);
        float2 acc1 = make_float2(0.f, 0.f);
        for (int k0 = 0; k0 < F1; k0 += 32) {
            float bias = sb[k0 + lane];
            float xa = fmaxf(in[(size_t)r0 * F1 + k0 + lane] + bias, 0.f);
            float xb = has1 ? fmaxf(in[(size_t)r1 * F1 + k0 + lane] + bias, 0.f) : 0.f;
#pragma unroll
            for (int j = 0; j < 32; j++) {
                float a = __shfl_sync(0xffffffffu, xa, j);
                float bv = __shfl_sync(0xffffffffu, xb, j);
                float2 w = sW2[(k0 + j) * 32 + lane];
                acc0.x += a * w.x;  acc0.y += a * w.y;
                acc1.x += bv * w.x; acc1.y += bv * w.y;
            }
        }
        ((float2*)out)[(size_t)r0 * 32 + lane] = acc0;
        if (has1) ((float2*)out)[(size_t)r1 * 32 + lane] = acc1;
    }
}

// ---------------------------------------------------------------------------
// Scatter layer 2: agg2[dst] += w * h2[src]  (F=64). Half-warp per edge.
// ---------------------------------------------------------------------------
__global__ void scatter64_kernel(const float* __restrict__ h,
                                 const int* __restrict__ ei,
                                 const float* __restrict__ ew,
                                 float* __restrict__ agg, int E) {
    int lane   = threadIdx.x & 31;
    int gwarp  = (blockIdx.x * blockDim.x + threadIdx.x) >> 5;
    int nwarps = (gridDim.x * blockDim.x) >> 5;
    int sub    = lane >> 4;      // which of 2 edges this half-warp handles
    int chunk  = lane & 15;      // float4 chunk within 64 floats

    for (int ebase = gwarp * 2; ebase < E; ebase += nwarps * 2) {
        int e = ebase + sub;
        if (e < E) {
            int src = ei[e];
            int dst = ei[E + e];
            float w = ew[e];
            float4 v = ((const float4*)(h + (size_t)src * F2))[chunk];
            v.x *= w; v.y *= w; v.z *= w; v.w *= w;
            float* ap = agg + (size_t)dst * F2 + chunk * 4;
            asm volatile("red.global.add.v4.f32 [%0], {%1,%2,%3,%4};"
                         :: "l"(ap), "f"(v.x), "f"(v.y), "f"(v.z), "f"(v.w)
                         : "memory");
        }
    }
}

// ---------------------------------------------------------------------------
// Final: out = relu(agg2 + b2) @ Wl + bl   (K=64, Nout=2). Thread per node.
// ---------------------------------------------------------------------------
__global__ void final_kernel(const float* __restrict__ agg2,
                             const float* __restrict__ b2,
                             const float* __restrict__ Wl,
                             const float* __restrict__ bl,
                             float* __restrict__ out, int nrows) {
    __shared__ float sW[F2 * 2];
    __shared__ float sb2[F2];
    __shared__ float sbl[2];
    if (threadIdx.x < F2 * 2) sW[threadIdx.x] = Wl[threadIdx.x];
    if (threadIdx.x < F2) sb2[threadIdx.x] = b2[threadIdx.x];
    if (threadIdx.x < 2) sbl[threadIdx.x] = bl[threadIdx.x];
    __syncthreads();

    int r = blockIdx.x * blockDim.x + threadIdx.x;
    if (r >= nrows) return;
    float a0 = sbl[0], a1 = sbl[1];
    const float4* row = (const float4*)(agg2 + (size_t)r * F2);
#pragma unroll
    for (int kk = 0; kk < 16; kk++) {
        float4 v = row[kk];
        int k = kk * 4;
        float v0 = fmaxf(v.x + sb2[k + 0], 0.f);
        float v1 = fmaxf(v.y + sb2[k + 1], 0.f);
        float v2 = fmaxf(v.z + sb2[k + 2], 0.f);
        float v3 = fmaxf(v.w + sb2[k + 3], 0.f);
        a0 += v0 * sW[(k + 0) * 2] + v1 * sW[(k + 1) * 2]
            + v2 * sW[(k + 2) * 2] + v3 * sW[(k + 3) * 2];
        a1 += v0 * sW[(k + 0) * 2 + 1] + v1 * sW[(k + 1) * 2 + 1]
            + v2 * sW[(k + 2) * 2 + 1] + v3 * sW[(k + 3) * 2 + 1];
    }
    out[(size_t)r * 2 + 0] = a0;
    out[(size_t)r * 2 + 1] = a1;
}

// ---------------------------------------------------------------------------
extern "C" void kernel_launch(void* const* d_in, const int* in_sizes, int n_in,
                              void* d_out, int out_size) {
    const float* x  = (const float*)d_in[0];
    const int*   ei = (const int*)d_in[1];
    const float* ew = (const float*)d_in[2];
    const float* W1 = (const float*)d_in[3];
    const float* b1 = (const float*)d_in[4];
    const float* W2 = (const float*)d_in[5];
    const float* b2 = (const float*)d_in[6];
    const float* Wl = (const float*)d_in[7];
    const float* bl = (const float*)d_in[8];
    float* out = (float*)d_out;

    int E = in_sizes[2];
    int n = in_sizes[0] / F1;

    float *h1p, *agg1p, *h2p, *agg2p;
    cudaGetSymbolAddress((void**)&h1p,   g_h1);
    cudaGetSymbolAddress((void**)&agg1p, g_agg1);
    cudaGetSymbolAddress((void**)&h2p,   g_h2);
    cudaGetSymbolAddress((void**)&agg2p, g_agg2);

    cudaFuncSetAttribute(gemm1_kernel,
                         cudaFuncAttributeMaxDynamicSharedMemorySize, 65536);

    cudaMemsetAsync(agg1p, 0, (size_t)n * F1 * sizeof(float), 0);
    cudaMemsetAsync(agg2p, 0, (size_t)n * F2 * sizeof(float), 0);

    // h1 = x @ W1
    int gemm1_blocks = ((n + 1) / 2 + 7) / 8;  // 8 warps/block, 2 rows/warp
    gemm1_kernel<<<gemm1_blocks, 256, 65536>>>(x, W1, h1p, n);

    // agg1[dst] += ew * h1[src]
    int sc1_blocks = (E + 7) / 8;              // 8 warps/block, 1 edge/warp
    scatter128_kernel<<<sc1_blocks, 256>>>(h1p, ei, ew, agg1p, E);

    // h2 = relu(agg1 + b1) @ W2
    int gemm2_blocks = ((n + 1) / 2 + 7) / 8;
    size_t smem2 = (F1 * F2 + F1) * sizeof(float);
    gemm2_kernel<<<gemm2_blocks, 256, smem2>>>(agg1p, W2, b1, h2p, n);

    // agg2[dst] += ew * h2[src]
    int sc2_blocks = (E + 15) / 16;            // 8 warps/block, 2 edges/warp
    scatter64_kernel<<<sc2_blocks, 256>>>(h2p, ei, ew, agg2p, E);

    // out = relu(agg2 + b2) @ Wl + bl
    final_kernel<<<(n + 255) / 256, 256>>>(agg2p, b2, Wl, bl, out, n);
}

// round 2
// speedup vs baseline: 1.2641x; 1.2641x over previous
#include <cuda_runtime.h>
#include <cstdint>

#define MAXN 50000
#define F1 128
#define F2 64
#define SLOTS 96   // max padded degree; Poisson(16) tail at 96 ~ 1e-40

// Scratch (__device__ globals; allocation-free rule)
__device__ float g_h1[MAXN * F1];      // x @ W1
__device__ float g_a1[MAXN * F1];      // relu(agg1 + b1)
__device__ float g_h2[MAXN * F2];      // a1 @ W2
__device__ int   g_cursor[MAXN];       // per-dst edge count / fill cursor
__device__ int2  g_slots[(size_t)MAXN * SLOTS];  // (src, w_bits) per dst

// ---------------------------------------------------------------------------
// Adjacency fill: one thread per edge. cursor must be zeroed first.
// ---------------------------------------------------------------------------
__global__ void fill_kernel(const int* __restrict__ ei,
                            const float* __restrict__ ew, int E,
                            int* __restrict__ cursor,
                            int2* __restrict__ slots) {
    int e = blockIdx.x * blockDim.x + threadIdx.x;
    if (e >= E) return;
    int src = ei[e];
    int dst = ei[E + e];
    float w = ew[e];
    int p = atomicAdd(&cursor[dst], 1);
    if (p < SLOTS)
        slots[(size_t)dst * SLOTS + p] = make_int2(src, __float_as_int(w));
}

// ---------------------------------------------------------------------------
// SGEMM: C[M,BN] = A[M,128] @ B[128,BN].  64-row block tiles, 256 threads,
// thread tile 4 x TN (TN = BN/16). K-tiles of 8 staged in smem.
// ---------------------------------------------------------------------------
template <int BN, int TN>
__global__ void sgemm_kernel(const float* __restrict__ A,
                             const float* __restrict__ B,
                             float* __restrict__ C, int M) {
    constexpr int KT = 8;
    __shared__ float As[KT][64 + 4];   // transposed, padded
    __shared__ float Bs[KT][BN];

    int tx = threadIdx.x % (BN / TN);  // 16 col groups
    int ty = threadIdx.x / (BN / TN);  // 16 row groups (TM=4)
    int row0 = blockIdx.x * 64;

    float acc[4][TN];
#pragma unroll
    for (int i = 0; i < 4; i++)
#pragma unroll
        for (int j = 0; j < TN; j++) acc[i][j] = 0.f;

    for (int k0 = 0; k0 < 128; k0 += KT) {
        for (int i = threadIdx.x; i < 64 * KT; i += 256) {
            int r = i / KT, kk = i % KT;
            int gr = row0 + r;
            As[kk][r] = (gr < M) ? A[(size_t)gr * 128 + k0 + kk] : 0.f;
        }
        for (int i = threadIdx.x; i < KT * BN; i += 256) {
            int kk = i / BN, c = i % BN;
            Bs[kk][c] = B[(size_t)(k0 + kk) * BN + c];
        }
        __syncthreads();
#pragma unroll
        for (int kk = 0; kk < KT; kk++) {
            float a[4], b[TN];
#pragma unroll
            for (int i = 0; i < 4; i++) a[i] = As[kk][ty * 4 + i];
#pragma unroll
            for (int j = 0; j < TN; j++) b[j] = Bs[kk][tx * TN + j];
#pragma unroll
            for (int i = 0; i < 4; i++)
#pragma unroll
                for (int j = 0; j < TN; j++) acc[i][j] += a[i] * b[j];
        }
        __syncthreads();
    }
#pragma unroll
    for (int i = 0; i < 4; i++) {
        int gr = row0 + ty * 4 + i;
        if (gr < M) {
#pragma unroll
            for (int j = 0; j < TN; j += 4)
                *(float4*)&C[(size_t)gr * BN + tx * TN + j] =
                    make_float4(acc[i][j], acc[i][j + 1], acc[i][j + 2], acc[i][j + 3]);
        }
    }
}

// ---------------------------------------------------------------------------
// Pull-aggregation layer 1: out[dst] = relu( sum_e w_e * h1[src_e] + b1 )
// One warp per dst. Lane holds float4 (4 of 128 cols).
// ---------------------------------------------------------------------------
__global__ void agg1_kernel(const float* __restrict__ h1,
                            const int* __restrict__ cursor,
                            const int2* __restrict__ slots,
                            const float* __restrict__ b1,
                            float* __restrict__ out, int n) {
    int lane = threadIdx.x & 31;
    int dst = (blockIdx.x * blockDim.x + threadIdx.x) >> 5;
    if (dst >= n) return;

    int deg = cursor[dst];
    const int2* row = slots + (size_t)dst * SLOTS;
    float4 acc = make_float4(0.f, 0.f, 0.f, 0.f);

    int i = 0;
    for (; i + 2 <= deg; i += 2) {
        int2 s0 = __ldg(&row[i]);
        int2 s1 = __ldg(&row[i + 1]);
        float4 v0 = ((const float4*)(h1 + (size_t)s0.x * F1))[lane];
        float4 v1 = ((const float4*)(h1 + (size_t)s1.x * F1))[lane];
        float w0 = __int_as_float(s0.y);
        float w1 = __int_as_float(s1.y);
        acc.x += w0 * v0.x; acc.y += w0 * v0.y;
        acc.z += w0 * v0.z; acc.w += w0 * v0.w;
        acc.x += w1 * v1.x; acc.y += w1 * v1.y;
        acc.z += w1 * v1.z; acc.w += w1 * v1.w;
    }
    if (i < deg) {
        int2 s0 = __ldg(&row[i]);
        float4 v0 = ((const float4*)(h1 + (size_t)s0.x * F1))[lane];
        float w0 = __int_as_float(s0.y);
        acc.x += w0 * v0.x; acc.y += w0 * v0.y;
        acc.z += w0 * v0.z; acc.w += w0 * v0.w;
    }

    float4 bb = ((const float4*)b1)[lane];
    acc.x = fmaxf(acc.x + bb.x, 0.f);
    acc.y = fmaxf(acc.y + bb.y, 0.f);
    acc.z = fmaxf(acc.z + bb.z, 0.f);
    acc.w = fmaxf(acc.w + bb.w, 0.f);
    ((float4*)(out + (size_t)dst * F1))[lane] = acc;
}

// ---------------------------------------------------------------------------
// Pull-aggregation layer 2 + final linear, fused:
//   t = relu( sum_e w_e * h2[src_e] + b2 )   (64 floats, float2 per lane)
//   out[dst, :] = t @ Wl + bl                (warp reduction)
// ---------------------------------------------------------------------------
__global__ void agg2_kernel(const float* __restrict__ h2,
                            const int* __restrict__ cursor,
                            const int2* __restrict__ slots,
                            const float* __restrict__ b2,
                            const float* __restrict__ Wl,
                            const float* __restrict__ bl,
                            float* __restrict__ out, int n) {
    int lane = threadIdx.x & 31;
    int dst = (blockIdx.x * blockDim.x + threadIdx.x) >> 5;
    if (dst >= n) return;

    int deg = cursor[dst];
    const int2* row = slots + (size_t)dst * SLOTS;
    float2 acc = make_float2(0.f, 0.f);

    int i = 0;
    for (; i + 2 <= deg; i += 2) {
        int2 s0 = __ldg(&row[i]);
        int2 s1 = __ldg(&row[i + 1]);
        float2 v0 = ((const float2*)(h2 + (size_t)s0.x * F2))[lane];
        float2 v1 = ((const float2*)(h2 + (size_t)s1.x * F2))[lane];
        float w0 = __int_as_float(s0.y);
        float w1 = __int_as_float(s1.y);
        acc.x += w0 * v0.x; acc.y += w0 * v0.y;
        acc.x += w1 * v1.x; acc.y += w1 * v1.y;
    }
    if (i < deg) {
        int2 s0 = __ldg(&row[i]);
        float2 v0 = ((const float2*)(h2 + (size_t)s0.x * F2))[lane];
        float w0 = __int_as_float(s0.y);
        acc.x += w0 * v0.x; acc.y += w0 * v0.y;
    }

    int c0 = lane * 2, c1 = lane * 2 + 1;
    float t0 = fmaxf(acc.x + __ldg(&b2[c0]), 0.f);
    float t1 = fmaxf(acc.y + __ldg(&b2[c1]), 0.f);

    float o0 = t0 * __ldg(&Wl[c0 * 2 + 0]) + t1 * __ldg(&Wl[c1 * 2 + 0]);
    float o1 = t0 * __ldg(&Wl[c0 * 2 + 1]) + t1 * __ldg(&Wl[c1 * 2 + 1]);
#pragma unroll
    for (int off = 16; off > 0; off >>= 1) {
        o0 += __shfl_down_sync(0xffffffffu, o0, off);
        o1 += __shfl_down_sync(0xffffffffu, o1, off);
    }
    if (lane == 0) {
        out[(size_t)dst * 2 + 0] = o0 + __ldg(&bl[0]);
        out[(size_t)dst * 2 + 1] = o1 + __ldg(&bl[1]);
    }
}

// ---------------------------------------------------------------------------
extern "C" void kernel_launch(void* const* d_in, const int* in_sizes, int n_in,
                              void* d_out, int out_size) {
    const float* x  = (const float*)d_in[0];
    const int*   ei = (const int*)d_in[1];
    const float* ew = (const float*)d_in[2];
    const float* W1 = (const float*)d_in[3];
    const float* b1 = (const float*)d_in[4];
    const float* W2 = (const float*)d_in[5];
    const float* b2 = (const float*)d_in[6];
    const float* Wl = (const float*)d_in[7];
    const float* bl = (const float*)d_in[8];
    float* out = (float*)d_out;

    int E = in_sizes[2];
    int n = in_sizes[0] / F1;

    float *h1p, *a1p, *h2p;
    int *curp;
    int2 *slotp;
    cudaGetSymbolAddress((void**)&h1p,   g_h1);
    cudaGetSymbolAddress((void**)&a1p,   g_a1);
    cudaGetSymbolAddress((void**)&h2p,   g_h2);
    cudaGetSymbolAddress((void**)&curp,  g_cursor);
    cudaGetSymbolAddress((void**)&slotp, g_slots);

    // Build adjacency (reused by both layers)
    cudaMemsetAsync(curp, 0, (size_t)n * sizeof(int), 0);
    fill_kernel<<<(E + 255) / 256, 256>>>(ei, ew, E, curp, slotp);

    // h1 = x @ W1
    sgemm_kernel<128, 8><<<(n + 63) / 64, 256>>>(x, W1, h1p, n);

    // a1 = relu(agg(h1) + b1)
    agg1_kernel<<<(n * 32 + 255) / 256, 256>>>(h1p, curp, slotp, b1, a1p, n);

    // h2 = a1 @ W2
    sgemm_kernel<64, 4><<<(n + 63) / 64, 256>>>(a1p, W2, h2p, n);

    // out = relu(agg(h2) + b2) @ Wl + bl
    agg2_kernel<<<(n * 32 + 255) / 256, 256>>>(h2p, curp, slotp, b2, Wl, bl, out, n);
}

// round 4
// speedup vs baseline: 2.0938x; 1.6563x over previous
#include <cuda_runtime.h>
#include <cuda_fp16.h>
#include <cstdint>

#define MAXN 50000
#define F1 128
#define F2 64
#define SLOTS 96   // padded max degree; Poisson(16) tail at 96 ~ 1e-40

// Scratch (__device__ globals; allocation-free rule)
__device__ __half g_h1h[(size_t)MAXN * F1];  // x @ W1, fp16 (gathered 16x)
__device__ float  g_a1[(size_t)MAXN * F1];   // relu(agg1 + b1), fp32
__device__ __half g_h2h[(size_t)MAXN * F2];  // a1 @ W2, fp16 (gathered 16x)
__device__ int    g_cursor[MAXN];
__device__ int2   g_slots[(size_t)MAXN * SLOTS];  // (src, w_bits)

// ---------------------------------------------------------------------------
// Adjacency fill: one thread per edge.
// ---------------------------------------------------------------------------
__global__ void fill_kernel(const int* __restrict__ ei,
                            const float* __restrict__ ew, int E,
                            int* __restrict__ cursor,
                            int2* __restrict__ slots) {
    int e = blockIdx.x * blockDim.x + threadIdx.x;
    if (e >= E) return;
    int src = ei[e];
    int dst = ei[E + e];
    float w = ew[e];
    int p = atomicAdd(&cursor[dst], 1);
    if (p < SLOTS)
        slots[(size_t)dst * SLOTS + p] = make_int2(src, __float_as_int(w));
}

// ---------------------------------------------------------------------------
// SGEMM (fp32 compute, fp16 output): C[M,BN] = A[M,128] @ B[128,BN]
// BM=128 rows/block, 256 threads, thread tile 8 x TNc (16x16 thread grid).
// K staged in tiles of 8; As transposed with pad to dodge bank conflicts.
// ---------------------------------------------------------------------------
template <int BN, int TNc>
__global__ void sgemm_f16out_kernel(const float* __restrict__ A,
                                    const float* __restrict__ B,
                                    __half* __restrict__ C, int M) {
    constexpr int KT = 8;
    __shared__ float As[KT][132];      // [kk][row], padded
    __shared__ float Bs[KT][BN];

    int tid = threadIdx.x;
    int tx = tid % 16;                 // col group (TNc cols)
    int ty = tid / 16;                 // row group (8 rows)
    int row0 = blockIdx.x * 128;

    float acc[8][TNc];
#pragma unroll
    for (int i = 0; i < 8; i++)
#pragma unroll
        for (int j = 0; j < TNc; j++) acc[i][j] = 0.f;

    for (int k0 = 0; k0 < 128; k0 += KT) {
        // Load A tile 128 x 8 (one float4 per thread: thread -> (row, half))
        {
            int r = tid >> 1;          // 0..127
            int h = tid & 1;           // which float4 of the row
            int gr = row0 + r;
            float4 v = make_float4(0.f, 0.f, 0.f, 0.f);
            if (gr < M)
                v = *(const float4*)&A[(size_t)gr * 128 + k0 + h * 4];
            As[h * 4 + 0][r] = v.x;
            As[h * 4 + 1][r] = v.y;
            As[h * 4 + 2][r] = v.z;
            As[h * 4 + 3][r] = v.w;
        }
        // Load B tile 8 x BN
        for (int i = tid; i < KT * BN / 4; i += 256) {
            int kk = i / (BN / 4);
            int c = (i % (BN / 4)) * 4;
            *(float4*)&Bs[kk][c] = *(const float4*)&B[(size_t)(k0 + kk) * BN + c];
        }
        __syncthreads();
#pragma unroll
        for (int kk = 0; kk < KT; kk++) {
            float a[8], b[TNc];
#pragma unroll
            for (int i = 0; i < 8; i += 4)
                *(float4*)&a[i] = *(const float4*)&As[kk][ty * 8 + i];
#pragma unroll
            for (int j = 0; j < TNc; j += 4)
                *(float4*)&b[j] = *(const float4*)&Bs[kk][tx * TNc + j];
#pragma unroll
            for (int i = 0; i < 8; i++)
#pragma unroll
                for (int j = 0; j < TNc; j++) acc[i][j] += a[i] * b[j];
        }
        __syncthreads();
    }
    // Store fp16
#pragma unroll
    for (int i = 0; i < 8; i++) {
        int gr = row0 + ty * 8 + i;
        if (gr < M) {
            half2 tmp[TNc / 2];
#pragma unroll
            for (int j = 0; j < TNc / 2; j++)
                tmp[j] = __floats2half2_rn(acc[i][2 * j], acc[i][2 * j + 1]);
            __half* dstp = C + (size_t)gr * BN + tx * TNc;
            if (TNc == 8) *(uint4*)dstp = *(uint4*)tmp;
            else          *(uint2*)dstp = *(uint2*)tmp;
        }
    }
}

// ---------------------------------------------------------------------------
// Pull-agg layer 1: a1[dst] = relu( sum_e w_e * h1[src_e] + b1 ), fp32 out.
// One warp per dst; lane holds 4 cols (uint2 = 4 halves).
// ---------------------------------------------------------------------------
__global__ void agg1_kernel(const __half* __restrict__ h1,
                            const int* __restrict__ cursor,
                            const int2* __restrict__ slots,
                            const float* __restrict__ b1,
                            float* __restrict__ out, int n) {
    int lane = threadIdx.x & 31;
    int dst = (blockIdx.x * blockDim.x + threadIdx.x) >> 5;
    if (dst >= n) return;

    int deg = cursor[dst];
    const int2* row = slots + (size_t)dst * SLOTS;
    float4 acc = make_float4(0.f, 0.f, 0.f, 0.f);

    int i = 0;
    for (; i + 2 <= deg; i += 2) {
        int2 s0 = __ldg(&row[i]);
        int2 s1 = __ldg(&row[i + 1]);
        uint2 r0 = ((const uint2*)(h1 + (size_t)s0.x * F1))[lane];
        uint2 r1 = ((const uint2*)(h1 + (size_t)s1.x * F1))[lane];
        float w0 = __int_as_float(s0.y);
        float w1 = __int_as_float(s1.y);
        float2 a0 = __half22float2(*(half2*)&r0.x);
        float2 a1v = __half22float2(*(half2*)&r0.y);
        float2 c0 = __half22float2(*(half2*)&r1.x);
        float2 c1 = __half22float2(*(half2*)&r1.y);
        acc.x += w0 * a0.x + w1 * c0.x;
        acc.y += w0 * a0.y + w1 * c0.y;
        acc.z += w0 * a1v.x + w1 * c1.x;
        acc.w += w0 * a1v.y + w1 * c1.y;
    }
    if (i < deg) {
        int2 s0 = __ldg(&row[i]);
        uint2 r0 = ((const uint2*)(h1 + (size_t)s0.x * F1))[lane];
        float w0 = __int_as_float(s0.y);
        float2 a0 = __half22float2(*(half2*)&r0.x);
        float2 a1v = __half22float2(*(half2*)&r0.y);
        acc.x += w0 * a0.x; acc.y += w0 * a0.y;
        acc.z += w0 * a1v.x; acc.w += w0 * a1v.y;
    }

    float4 bb = __ldg(&((const float4*)b1)[lane]);
    acc.x = fmaxf(acc.x + bb.x, 0.f);
    acc.y = fmaxf(acc.y + bb.y, 0.f);
    acc.z = fmaxf(acc.z + bb.z, 0.f);
    acc.w = fmaxf(acc.w + bb.w, 0.f);
    ((float4*)(out + (size_t)dst * F1))[lane] = acc;
}

// ---------------------------------------------------------------------------
// Pull-agg layer 2 + final linear, fused:
//   t = relu( sum_e w_e * h2[src_e] + b2 ); out[dst,:] = t @ Wl + bl
// One warp per dst; lane holds 2 cols (half2).
// ---------------------------------------------------------------------------
__global__ void agg2_kernel(const __half* __restrict__ h2,
                            const int* __restrict__ cursor,
                            const int2* __restrict__ slots,
                            const float* __restrict__ b2,
                            const float* __restrict__ Wl,
                            const float* __restrict__ bl,
                            float* __restrict__ out, int n) {
    int lane = threadIdx.x & 31;
    int dst = (blockIdx.x * blockDim.x + threadIdx.x) >> 5;
    if (dst >= n) return;

    int deg = cursor[dst];
    const int2* row = slots + (size_t)dst * SLOTS;
    float2 acc = make_float2(0.f, 0.f);

    int i = 0;
    for (; i + 2 <= deg; i += 2) {
        int2 s0 = __ldg(&row[i]);
        int2 s1 = __ldg(&row[i + 1]);
        uint r0 = ((const uint*)(h2 + (size_t)s0.x * F2))[lane];
        uint r1 = ((const uint*)(h2 + (size_t)s1.x * F2))[lane];
        float w0 = __int_as_float(s0.y);
        float w1 = __int_as_float(s1.y);
        float2 v0 = __half22float2(*(half2*)&r0);
        float2 v1 = __half22float2(*(half2*)&r1);
        acc.x += w0 * v0.x + w1 * v1.x;
        acc.y += w0 * v0.y + w1 * v1.y;
    }
    if (i < deg) {
        int2 s0 = __ldg(&row[i]);
        uint r0 = ((const uint*)(h2 + (size_t)s0.x * F2))[lane];
        float w0 = __int_as_float(s0.y);
        float2 v0 = __half22float2(*(half2*)&r0);
        acc.x += w0 * v0.x; acc.y += w0 * v0.y;
    }

    int c0 = lane * 2, c1 = lane * 2 + 1;
    float t0 = fmaxf(acc.x + __ldg(&b2[c0]), 0.f);
    float t1 = fmaxf(acc.y + __ldg(&b2[c1]), 0.f);

    float o0 = t0 * __ldg(&Wl[c0 * 2 + 0]) + t1 * __ldg(&Wl[c1 * 2 + 0]);
    float o1 = t0 * __ldg(&Wl[c0 * 2 + 1]) + t1 * __ldg(&Wl[c1 * 2 + 1]);
#pragma unroll
    for (int off = 16; off > 0; off >>= 1) {
        o0 += __shfl_down_sync(0xffffffffu, o0, off);
        o1 += __shfl_down_sync(0xffffffffu, o1, off);
    }
    if (lane == 0) {
        out[(size_t)dst * 2 + 0] = o0 + __ldg(&bl[0]);
        out[(size_t)dst * 2 + 1] = o1 + __ldg(&bl[1]);
    }
}

// ---------------------------------------------------------------------------
extern "C" void kernel_launch(void* const* d_in, const int* in_sizes, int n_in,
                              void* d_out, int out_size) {
    const float* x  = (const float*)d_in[0];
    const int*   ei = (const int*)d_in[1];
    const float* ew = (const float*)d_in[2];
    const float* W1 = (const float*)d_in[3];
    const float* b1 = (const float*)d_in[4];
    const float* W2 = (const float*)d_in[5];
    const float* b2 = (const float*)d_in[6];
    const float* Wl = (const float*)d_in[7];
    const float* bl = (const float*)d_in[8];
    float* out = (float*)d_out;

    int E = in_sizes[2];
    int n = in_sizes[0] / F1;

    __half *h1p, *h2p;
    float *a1p;
    int *curp;
    int2 *slotp;
    cudaGetSymbolAddress((void**)&h1p,   g_h1h);
    cudaGetSymbolAddress((void**)&a1p,   g_a1);
    cudaGetSymbolAddress((void**)&h2p,   g_h2h);
    cudaGetSymbolAddress((void**)&curp,  g_cursor);
    cudaGetSymbolAddress((void**)&slotp, g_slots);

    // Adjacency (shared by both layers)
    cudaMemsetAsync(curp, 0, (size_t)n * sizeof(int), 0);
    fill_kernel<<<(E + 255) / 256, 256>>>(ei, ew, E, curp, slotp);

    // h1 = x @ W1  (fp16 out)
    sgemm_f16out_kernel<128, 8><<<(n + 127) / 128, 256>>>(x, W1, h1p, n);

    // a1 = relu(agg(h1) + b1)
    agg1_kernel<<<(n * 32 + 255) / 256, 256>>>(h1p, curp, slotp, b1, a1p, n);

    // h2 = a1 @ W2  (fp16 out)
    sgemm_f16out_kernel<64, 4><<<(n + 127) / 128, 256>>>(a1p, W2, h2p, n);

    // out = relu(agg(h2) + b2) @ Wl + bl
    agg2_kernel<<<(n * 32 + 255) / 256, 256>>>(h2p, curp, slotp, b2, Wl, bl, out, n);
}